// round 8
// baseline (speedup 1.0000x reference)
#include <cuda_runtime.h>
#include <cuda_fp16.h>
#include <cstdint>
#include <cstddef>

#define T_STEPS 512
#define BATCH   64
#define HID     512
#define GATES   2048   // 4*HID, interleaved j' = h*4 + gate (f,i,g,o)
#define DIN     512
#define NBLK    128    // 32 col-groups x 4 batch-groups
#define NTHR    384    // warps 0-7: h crew, warps 8-11: x crew

// ---------------- device scratch --------------------------------------------
__device__ __half g_h16[2 * BATCH * HID];  // fp16 h double buffer
__device__ unsigned int g_bar4[4 * 32];    // per batch-group barrier counters

// ---------------- helpers ----------------------------------------------------
__device__ __forceinline__ uint32_t smem_u32(const void* p) {
    uint32_t a;
    asm("{ .reg .u64 t; cvta.to.shared.u64 t, %1; cvt.u32.u64 %0, t; }"
        : "=r"(a) : "l"(p));
    return a;
}
__device__ __forceinline__ float sigf(float x) {
    return __fdividef(1.0f, 1.0f + __expf(-x));
}
__device__ __forceinline__ float tanhfast(float x) {
    return fmaf(2.0f, sigf(2.0f * x), -1.0f);
}
__device__ __forceinline__ void ldsm4(uint32_t& r0, uint32_t& r1, uint32_t& r2,
                                      uint32_t& r3, uint32_t addr) {
    asm volatile("ldmatrix.sync.aligned.m8n8.x4.shared.b16 {%0,%1,%2,%3}, [%4];"
                 : "=r"(r0), "=r"(r1), "=r"(r2), "=r"(r3) : "r"(addr));
}
__device__ __forceinline__ void hmma(float* c,
                                     uint32_t a0, uint32_t a1, uint32_t a2, uint32_t a3,
                                     uint32_t b0, uint32_t b1) {
    asm volatile("mma.sync.aligned.m16n8k16.row.col.f32.f16.f16.f32 "
                 "{%0,%1,%2,%3}, {%4,%5,%6,%7}, {%8,%9}, {%0,%1,%2,%3};"
                 : "+f"(c[0]), "+f"(c[1]), "+f"(c[2]), "+f"(c[3])
                 : "r"(a0), "r"(a1), "r"(a2), "r"(a3), "r"(b0), "r"(b1));
}
__device__ __forceinline__ uint32_t pkh2(float x, float y) {
    __half2 h = __floats2half2_rn(x, y);
    return *(uint32_t*)&h;
}

// dynamic smem layout (after 1KB alignment pad):
//   [0,    16K)  hA   : h(t-1) tile [16 r][512 halfs], xor-swizzled
//   [16K,  32K)  xA0  : x tile buffer 0
//   [32K,  48K)  xA1  : x tile buffer 1
//   [48K, 112K)  WxF  : Wx B-frags  uint4[(wx*32+ks)*32 + lane]
//   [112K,116K)  gxs0 : Gx preacts buffer 0 (float4[256], pre-shuffle layout)
//   [116K,120K)  gxs1 : Gx preacts buffer 1
//   [120K,124K)  exh  : h k-half exchange (float4[256])
#define SMEM_BYTES (124 * 1024 + 1024)

// ---------------- fused warp-specialized persistent kernel -------------------
// 128 blocks: cb=bx&31 -> gate cols [64cb,64cb+64), nb=bx>>5 -> batch rows
// [16nb,16nb+16).
// h crew (warps 0-7): warp w = (u=w>>1 colpair, kv=w&1 k-half); Wh frags in
//   regs; per step: spin -> gather h -> 16x(ldsm+2 hmma) -> k-half exchange ->
//   +Gx(t) from gxs -> activations -> store h -> signal.
// x crew (warps 8-11): warp wx owns 16 cols, full K; Wx frags in smem; per
//   step: 32x(ldsm+LDS+2 hmma) on x(t+1) -> write gxs[(t+1)&1] -> (after
//   release) gather x(t+2) in the spin shadow.
__global__ void __launch_bounds__(NTHR, 1) lstm_kernel(
    float* __restrict__ out, int write_tail, const float* __restrict__ X,
    const float* __restrict__ Wf, const float* __restrict__ Wi,
    const float* __restrict__ Wg, const float* __restrict__ Wo,
    const float* __restrict__ bfp, const float* __restrict__ bip,
    const float* __restrict__ bgp, const float* __restrict__ bop) {
    extern __shared__ char dynsm[];
    __shared__ __align__(16) float hsm[16 * 20];

    const uint32_t sb0 = smem_u32(dynsm);
    const uint32_t sb  = (sb0 + 1023u) & ~1023u;
    char* const basep = dynsm + (sb - sb0);
    char* const hAp   = basep;
    char* const xA0p  = basep + 16 * 1024;
    char* const xA1p  = basep + 32 * 1024;
    uint4*  const wxf4 = (uint4*)(basep + 48 * 1024);
    float4* const gxs0 = (float4*)(basep + 112 * 1024);
    float4* const gxs1 = (float4*)(basep + 116 * 1024);
    float4* const exh  = (float4*)(basep + 120 * 1024);
    const uint32_t hA_addr  = sb;
    const uint32_t xA0_addr = sb + 16 * 1024;
    const uint32_t xA1_addr = sb + 32 * 1024;

    const int tid  = threadIdx.x;
    const int w    = tid >> 5;
    const int lane = tid & 31;
    const bool is_h = (w < 8);
    const int cb   = blockIdx.x & 31;
    const int nb   = blockIdx.x >> 5;
    const int c0g  = cb * 64;
    const int h0   = cb * 16;
    const int b0   = nb * 16;
    unsigned int* barp = &g_bar4[nb * 32];

    const int g8 = lane >> 2;
    const int tg = lane & 3;

    // ---- prologue: Wh B-frags (h crew regs) / Wx B-frags (x crew -> smem) -----
    uint32_t Bf[16][2][2];
    int u = 0, kv = 0, wx = 0;
    if (is_h) {
        u  = w >> 1;
        kv = w & 1;
        const int j0c = c0g + 16 * u + g8;
        const int gt  = j0c & 3;
        const int hh0 = j0c >> 2;
        const float* Wsel = (gt == 0) ? Wf : (gt == 1) ? Wi : (gt == 2) ? Wg : Wo;
        const float* w0 = Wsel + (size_t)hh0 * (DIN + HID) + DIN;
        const float* w1 = Wsel + (size_t)(hh0 + 2) * (DIN + HID) + DIN;
#pragma unroll
        for (int ks = 0; ks < 16; ks++) {
            const int k0 = (kv * 16 + ks) * 16 + 2 * tg;
            float2 a0 = *(const float2*)(w0 + k0);
            float2 b0v = *(const float2*)(w0 + k0 + 8);
            Bf[ks][0][0] = pkh2(a0.x, a0.y);
            Bf[ks][0][1] = pkh2(b0v.x, b0v.y);
            float2 a1 = *(const float2*)(w1 + k0);
            float2 b1v = *(const float2*)(w1 + k0 + 8);
            Bf[ks][1][0] = pkh2(a1.x, a1.y);
            Bf[ks][1][1] = pkh2(b1v.x, b1v.y);
        }
    } else {
        wx = w - 8;
        const int j0c = c0g + 16 * wx + g8;
        const int gt  = j0c & 3;
        const int hh0 = j0c >> 2;
        const float* Wsel = (gt == 0) ? Wf : (gt == 1) ? Wi : (gt == 2) ? Wg : Wo;
        const float* w0 = Wsel + (size_t)hh0 * (DIN + HID);
        const float* w1 = Wsel + (size_t)(hh0 + 2) * (DIN + HID);
#pragma unroll
        for (int ks = 0; ks < 32; ks++) {
            const int k0 = ks * 16 + 2 * tg;
            float2 a0 = *(const float2*)(w0 + k0);
            float2 b0v = *(const float2*)(w0 + k0 + 8);
            float2 a1 = *(const float2*)(w1 + k0);
            float2 b1v = *(const float2*)(w1 + k0 + 8);
            wxf4[(wx * 32 + ks) * 32 + lane] =
                make_uint4(pkh2(a0.x, a0.y), pkh2(b0v.x, b0v.y),
                           pkh2(a1.x, a1.y), pkh2(b1v.x, b1v.y));
        }
    }
    // zero hA (t=0 h-MMA reads zeros)
    for (int i = tid; i < 1024; i += NTHR)
        *(uint4*)(hAp + i * 16) = make_uint4(0u, 0u, 0u, 0u);

    const uint32_t lrow  = lane & 15;
    const uint32_t lrow7 = lrow & 7;
    const uint32_t lbase  = hA_addr + lrow * 1024;
    const uint32_t x0base = xA0_addr + lrow * 1024;
    const uint32_t x1base = xA1_addr + lrow * 1024;
    const uint32_t csel  = lane >> 4;
    const uint32_t kofs  = (uint32_t)(kv * 16);

    // epilogue mapping (h crew; owned cols after exchange = c0g + 8w)
    const int lc    = 2 * w + (tg >> 1);
    const int myrow = g8 + ((tg & 1) ? 8 : 0);
    const int j0    = c0g + 8 * w + (tg & 2) * 2;
    const int hcell = is_h ? (j0 >> 2) : 0;
    const float4 bb = make_float4(bfp[hcell], bip[hcell], bgp[hcell], bop[hcell]);
    float c_st = 0.f;
    const int wrow = tid >> 2;
    const int wc4  = (tid & 3) << 2;

    // x crew gather: 128 threads, 8 chunks each
#define GATHER_X(tt, dstp) do {                                                \
    const float* xsrc = X + ((size_t)(tt) * BATCH + b0) * DIN;                 \
    const int xtid_ = tid - 256;                                               \
    _Pragma("unroll")                                                          \
    for (int i_ = 0; i_ < 8; i_++) {                                           \
        int idx_ = xtid_ + i_ * 128;                                           \
        int r_   = idx_ >> 6;                                                  \
        int c_   = idx_ & 63;                                                  \
        const float* p_ = xsrc + (size_t)r_ * DIN + c_ * 8;                    \
        float4 u_ = __ldcg((const float4*)p_);                                 \
        float4 v_ = __ldcg((const float4*)(p_ + 4));                           \
        *(uint4*)((dstp) + r_ * 1024 + ((c_ ^ (r_ & 7)) << 4)) =               \
            make_uint4(pkh2(u_.x, u_.y), pkh2(u_.z, u_.w),                     \
                       pkh2(v_.x, v_.y), pkh2(v_.z, v_.w));                    \
    }                                                                          \
} while (0)

    // x k-loop: reads xA at xbase_, Wx frags from smem, full K, no exchange
#define X_KLOOP(xbase_, gxd_) do {                                             \
    float qx0_[4] = {0.f, 0.f, 0.f, 0.f}, qx1_[4] = {0.f, 0.f, 0.f, 0.f};      \
    _Pragma("unroll")                                                          \
    for (int ks_ = 0; ks_ < 32; ks_++) {                                       \
        uint32_t kk_ = ((uint32_t)(2 * ks_) + csel) ^ lrow7;                   \
        uint32_t a0_, a1_, a2_, a3_;                                           \
        ldsm4(a0_, a1_, a2_, a3_, (xbase_) + (kk_ << 4));                      \
        uint4 wv_ = wxf4[(wx * 32 + ks_) * 32 + lane];                         \
        hmma(qx0_, a0_, a1_, a2_, a3_, wv_.x, wv_.y);                          \
        hmma(qx1_, a0_, a1_, a2_, a3_, wv_.z, wv_.w);                          \
    }                                                                          \
    (gxd_)[(2 * wx + 0) * 32 + lane] =                                         \
        make_float4(qx0_[0], qx0_[1], qx0_[2], qx0_[3]);                       \
    (gxd_)[(2 * wx + 1) * 32 + lane] =                                         \
        make_float4(qx1_[0], qx1_[1], qx1_[2], qx1_[3]);                       \
} while (0)

    // ---- prologue: x crew gathers x(0), computes Gx(0), gathers x(1) ----------
    if (!is_h) GATHER_X(0, xA0p);
    __syncthreads();
    if (!is_h) {
        X_KLOOP(x0base, gxs0);
        GATHER_X(1, xA1p);
    }
    __syncthreads();

    for (int t = 0; t < T_STEPS; t++) {
        // ---- phase 1: h crew spins + gathers h(t-1) ----------------------------
        if (is_h && t > 0) {
            unsigned int target = (unsigned int)t * 32u;
            unsigned int v;
            do {
                asm volatile("ld.acquire.gpu.u32 %0, [%1];" : "=r"(v) : "l"(barp));
            } while (v < target);
            const __half* hsrc = g_h16 + (size_t)((t - 1) & 1) * BATCH * HID
                               + (size_t)b0 * HID;
#pragma unroll
            for (int i = 0; i < 4; i++) {
                int idx = tid + i * 256;
                int r   = idx >> 6;
                int c   = idx & 63;
                uint4 vv = __ldcg((const uint4*)(hsrc + (size_t)r * HID + c * 8));
                *(uint4*)(hAp + r * 1024 + ((c ^ (r & 7)) << 4)) = vv;
            }
        }
        __syncthreads();   // sync_A: hA ready; xA(t+1) ready (gathered step t-1)

        // ---- phase 2 -----------------------------------------------------------
        float qh0[4] = {0.f, 0.f, 0.f, 0.f}, qh1[4] = {0.f, 0.f, 0.f, 0.f};
        if (is_h) {
#pragma unroll
            for (int ks = 0; ks < 16; ks++) {
                uint32_t kk = (2 * (kofs + ks) + csel) ^ lrow7;
                uint32_t a0, a1, a2, a3;
                ldsm4(a0, a1, a2, a3, lbase + (kk << 4));
                hmma(qh0, a0, a1, a2, a3, Bf[ks][0][0], Bf[ks][0][1]);
                hmma(qh1, a0, a1, a2, a3, Bf[ks][1][0], Bf[ks][1][1]);
            }
            float* gh = kv ? qh0 : qh1;
            exh[w * 32 + lane] = make_float4(gh[0], gh[1], gh[2], gh[3]);
        } else if (t + 1 < T_STEPS) {
            const uint32_t xbase = ((t + 1) & 1) ? x1base : x0base;
            float4* gxd = ((t + 1) & 1) ? gxs1 : gxs0;
            X_KLOOP(xbase, gxd);
        }
        __syncthreads();   // sync_B: exh + gxs[(t+1)&1] ready

        // ---- phase 3: h crew epilogue ------------------------------------------
        if (is_h) {
            float4 ph = exh[(w ^ 1) * 32 + lane];
            float4 gx = ((t & 1) ? gxs1 : gxs0)[w * 32 + lane];
            float* kh = kv ? qh1 : qh0;
            float c0  = kh[0] + ph.x + gx.x;
            float c1  = kh[1] + ph.y + gx.y;
            float c2v = kh[2] + ph.z + gx.z;
            float c3  = kh[3] + ph.w + gx.w;

            float s0 = __shfl_xor_sync(0xffffffffu, c0, 1);
            float s1 = __shfl_xor_sync(0xffffffffu, c1, 1);
            float s2 = __shfl_xor_sync(0xffffffffu, c2v, 1);
            float s3 = __shfl_xor_sync(0xffffffffu, c3, 1);
            float pf, pi, pg, po;
            if (tg & 1) { pf = s2; pi = s3; pg = c2v; po = c3; }
            else        { pf = c0; pi = c1; pg = s0;  po = s1; }
            pf += bb.x;
            pi += bb.y;
            pg += bb.z;
            po += bb.w;

            float f  = sigf(pf);
            float ii = sigf(pi);
            float gv = tanhfast(pg);
            float oo = sigf(po);
            c_st = f * c_st + ii * gv;
            float hv = oo * tanhfast(c_st);
            hsm[myrow * 20 + lc] = hv;
        }
        __syncthreads();   // sync_C: hsm ready

        // ---- writers: fp16 h (critical) -> signal -> fp32 out ------------------
        float4 v4;
        if (tid < 64) {
            v4 = *(const float4*)&hsm[wrow * 20 + wc4];
            uint2 pk;
            pk.x = pkh2(v4.x, v4.y);
            pk.y = pkh2(v4.z, v4.w);
            *(uint2*)(g_h16 + (size_t)(t & 1) * BATCH * HID
                      + (size_t)(b0 + wrow) * HID + h0 + wc4) = pk;
        }
        if (t + 1 < T_STEPS) {
            __syncthreads();   // sync_D: h16 stores done
            if (tid == 0)
                asm volatile("red.release.gpu.global.add.u32 [%0], %1;"
                             :: "l"(barp), "r"(1u) : "memory");
        }
        if (tid < 64) {
            *(float4*)(out + ((size_t)t * BATCH + b0 + wrow) * HID + h0 + wc4) = v4;
            if (write_tail && t == T_STEPS - 1) {
                *(float4*)(out + (size_t)T_STEPS * BATCH * HID
                           + (size_t)(b0 + wrow) * HID + h0 + wc4) = v4;
            }
        }

        // ---- shadow: x crew gathers x(t+2) during other blocks' catch-up -------
        if (!is_h && t + 2 < T_STEPS) {
            char* xdst = (t & 1) ? xA1p : xA0p;
            GATHER_X(t + 2, xdst);
        }
    }

    // ---- tail: c state ---------------------------------------------------------
    if (write_tail) {
        __syncthreads();
        if (is_h) hsm[myrow * 20 + lc] = c_st;
        __syncthreads();
        if (tid < 64) {
            float4 v4 = *(const float4*)&hsm[wrow * 20 + wc4];
            *(float4*)(out + (size_t)(T_STEPS + 1) * BATCH * HID
                       + (size_t)(b0 + wrow) * HID + h0 + wc4) = v4;
        }
    }
}

// ---------------- launch ------------------------------------------------------
extern "C" void kernel_launch(void* const* d_in, const int* in_sizes, int n_in,
                              void* d_out, int out_size) {
    const float* x  = (const float*)d_in[0];
    const float* Wf = (const float*)d_in[1];
    const float* bf = (const float*)d_in[2];
    const float* Wi = (const float*)d_in[3];
    const float* bi = (const float*)d_in[4];
    const float* Wg = (const float*)d_in[5];
    const float* bg = (const float*)d_in[6];
    const float* Wo = (const float*)d_in[7];
    const float* bo = (const float*)d_in[8];
    float* out = (float*)d_out;

    const long long tbh = (long long)T_STEPS * BATCH * HID;
    int write_tail = ((long long)out_size >= tbh + 2LL * BATCH * HID) ? 1 : 0;

    void* barp = nullptr;
    cudaGetSymbolAddress(&barp, g_bar4);
    cudaMemsetAsync(barp, 0, sizeof(unsigned int) * 4 * 32, 0);

    cudaFuncSetAttribute(lstm_kernel, cudaFuncAttributeMaxDynamicSharedMemorySize,
                         SMEM_BYTES);
    lstm_kernel<<<NBLK, NTHR, SMEM_BYTES>>>(out, write_tail, x,
                                            Wf, Wi, Wg, Wo, bf, bi, bg, bo);
}

// round 9
// speedup vs baseline: 1.3771x; 1.3771x over previous
#include <cuda_runtime.h>
#include <cuda_fp16.h>
#include <cstdint>
#include <cstddef>

#define T_STEPS 512
#define BATCH   64
#define HID     512
#define GATES   2048   // 4*HID, interleaved j' = h*4 + gate (f,i,g,o)
#define DIN     512
#define NBLK    128    // 32 col-groups x 4 batch-groups
#define NTHR    384    // warps 0-7: h crew, warps 8-11: x crew

// ---------------- device scratch --------------------------------------------
__device__ __half g_h16[2 * BATCH * HID];  // fp16 h double buffer
__device__ unsigned int g_bar4[4 * 32];    // per batch-group barrier counters

// ---------------- helpers ----------------------------------------------------
__device__ __forceinline__ uint32_t smem_u32(const void* p) {
    uint32_t a;
    asm("{ .reg .u64 t; cvta.to.shared.u64 t, %1; cvt.u32.u64 %0, t; }"
        : "=r"(a) : "l"(p));
    return a;
}
__device__ __forceinline__ float sigf(float x) {
    return __fdividef(1.0f, 1.0f + __expf(-x));
}
__device__ __forceinline__ float tanhfast(float x) {
    return fmaf(2.0f, sigf(2.0f * x), -1.0f);
}
__device__ __forceinline__ void ldsm4(uint32_t& r0, uint32_t& r1, uint32_t& r2,
                                      uint32_t& r3, uint32_t addr) {
    asm volatile("ldmatrix.sync.aligned.m8n8.x4.shared.b16 {%0,%1,%2,%3}, [%4];"
                 : "=r"(r0), "=r"(r1), "=r"(r2), "=r"(r3) : "r"(addr));
}
__device__ __forceinline__ void hmma(float* c,
                                     uint32_t a0, uint32_t a1, uint32_t a2, uint32_t a3,
                                     uint32_t b0, uint32_t b1) {
    asm volatile("mma.sync.aligned.m16n8k16.row.col.f32.f16.f16.f32 "
                 "{%0,%1,%2,%3}, {%4,%5,%6,%7}, {%8,%9}, {%0,%1,%2,%3};"
                 : "+f"(c[0]), "+f"(c[1]), "+f"(c[2]), "+f"(c[3])
                 : "r"(a0), "r"(a1), "r"(a2), "r"(a3), "r"(b0), "r"(b1));
}
__device__ __forceinline__ uint32_t pkh2(float x, float y) {
    __half2 h = __floats2half2_rn(x, y);
    return *(uint32_t*)&h;
}
#define HBAR() asm volatile("bar.sync 1, 256;" ::: "memory")   // h crew only

// dynamic smem layout (after 1KB alignment pad):
//   [0,    16K)  hA   : h(t-1) tile [16 r][512 halfs], xor-swizzled
//   [16K,  32K)  xA0  : x tile buffer 0
//   [32K,  48K)  xA1  : x tile buffer 1
//   [48K, 112K)  WxF  : Wx B-frags  uint4[(wx*32+ks)*32 + lane]
//   [112K,116K)  gxs0 : Gx preacts buffer 0 (float4[256], pre-shuffle layout)
//   [116K,120K)  gxs1 : Gx preacts buffer 1
//   [120K,124K)  exh  : h k-half exchange (float4[256])
#define SMEM_BYTES (124 * 1024 + 1024)

// ---------------- fused warp-specialized persistent kernel -------------------
// h crew (warps 0-7, named barrier 1): spin -> gather h -> 16x(ldsm+2hmma) ->
//   exchange -> epilogue(+gxs[t&1]) -> store h16 -> signal.
// x crew (warps 8-11): X_KLOOP -> gxs[(t+1)&1]; gather x(t+2).
// ONE joint __syncthreads per step (end) orders the double-buffered gxs.
__global__ void __launch_bounds__(NTHR, 1) lstm_kernel(
    float* __restrict__ out, int write_tail, const float* __restrict__ X,
    const float* __restrict__ Wf, const float* __restrict__ Wi,
    const float* __restrict__ Wg, const float* __restrict__ Wo,
    const float* __restrict__ bfp, const float* __restrict__ bip,
    const float* __restrict__ bgp, const float* __restrict__ bop) {
    extern __shared__ char dynsm[];
    __shared__ __align__(16) float hsm[16 * 20];

    const uint32_t sb0 = smem_u32(dynsm);
    const uint32_t sb  = (sb0 + 1023u) & ~1023u;
    char* const basep = dynsm + (sb - sb0);
    char* const hAp   = basep;
    char* const xA0p  = basep + 16 * 1024;
    char* const xA1p  = basep + 32 * 1024;
    uint4*  const wxf4 = (uint4*)(basep + 48 * 1024);
    float4* const gxs0 = (float4*)(basep + 112 * 1024);
    float4* const gxs1 = (float4*)(basep + 116 * 1024);
    float4* const exh  = (float4*)(basep + 120 * 1024);
    const uint32_t hA_addr  = sb;
    const uint32_t xA0_addr = sb + 16 * 1024;
    const uint32_t xA1_addr = sb + 32 * 1024;

    const int tid  = threadIdx.x;
    const int w    = tid >> 5;
    const int lane = tid & 31;
    const bool is_h = (w < 8);
    const int cb   = blockIdx.x & 31;
    const int nb   = blockIdx.x >> 5;
    const int c0g  = cb * 64;
    const int h0   = cb * 16;
    const int b0   = nb * 16;
    unsigned int* barp = &g_bar4[nb * 32];

    const int g8 = lane >> 2;
    const int tg = lane & 3;

    // ---- prologue: Wh B-frags (h crew regs) / Wx B-frags (x crew -> smem) -----
    uint32_t Bf[16][2][2];
    int u = 0, kv = 0, wx = 0;
    if (is_h) {
        u  = w >> 1;
        kv = w & 1;
        const int j0c = c0g + 16 * u + g8;
        const int gt  = j0c & 3;
        const int hh0 = j0c >> 2;
        const float* Wsel = (gt == 0) ? Wf : (gt == 1) ? Wi : (gt == 2) ? Wg : Wo;
        const float* w0 = Wsel + (size_t)hh0 * (DIN + HID) + DIN;
        const float* w1 = Wsel + (size_t)(hh0 + 2) * (DIN + HID) + DIN;
#pragma unroll
        for (int ks = 0; ks < 16; ks++) {
            const int k0 = (kv * 16 + ks) * 16 + 2 * tg;
            float2 a0 = *(const float2*)(w0 + k0);
            float2 b0v = *(const float2*)(w0 + k0 + 8);
            Bf[ks][0][0] = pkh2(a0.x, a0.y);
            Bf[ks][0][1] = pkh2(b0v.x, b0v.y);
            float2 a1 = *(const float2*)(w1 + k0);
            float2 b1v = *(const float2*)(w1 + k0 + 8);
            Bf[ks][1][0] = pkh2(a1.x, a1.y);
            Bf[ks][1][1] = pkh2(b1v.x, b1v.y);
        }
    } else {
        wx = w - 8;
        const int j0c = c0g + 16 * wx + g8;
        const int gt  = j0c & 3;
        const int hh0 = j0c >> 2;
        const float* Wsel = (gt == 0) ? Wf : (gt == 1) ? Wi : (gt == 2) ? Wg : Wo;
        const float* w0 = Wsel + (size_t)hh0 * (DIN + HID);
        const float* w1 = Wsel + (size_t)(hh0 + 2) * (DIN + HID);
#pragma unroll
        for (int ks = 0; ks < 32; ks++) {
            const int k0 = ks * 16 + 2 * tg;
            float2 a0 = *(const float2*)(w0 + k0);
            float2 b0v = *(const float2*)(w0 + k0 + 8);
            float2 a1 = *(const float2*)(w1 + k0);
            float2 b1v = *(const float2*)(w1 + k0 + 8);
            wxf4[(wx * 32 + ks) * 32 + lane] =
                make_uint4(pkh2(a0.x, a0.y), pkh2(b0v.x, b0v.y),
                           pkh2(a1.x, a1.y), pkh2(b1v.x, b1v.y));
        }
    }
    // zero hA (t=0 h-MMA reads zeros)
    for (int i = tid; i < 1024; i += NTHR)
        *(uint4*)(hAp + i * 16) = make_uint4(0u, 0u, 0u, 0u);

    const uint32_t lrow  = lane & 15;
    const uint32_t lrow7 = lrow & 7;
    const uint32_t lbase  = hA_addr + lrow * 1024;
    const uint32_t x0base = xA0_addr + lrow * 1024;
    const uint32_t x1base = xA1_addr + lrow * 1024;
    const uint32_t csel  = lane >> 4;
    const uint32_t kofs  = (uint32_t)(kv * 16);

    // epilogue mapping (h crew)
    const int lc    = 2 * w + (tg >> 1);
    const int myrow = g8 + ((tg & 1) ? 8 : 0);
    const int j0    = c0g + 8 * w + (tg & 2) * 2;
    const int hcell = is_h ? (j0 >> 2) : 0;
    const float4 bb = make_float4(bfp[hcell], bip[hcell], bgp[hcell], bop[hcell]);
    float c_st = 0.f;
    const int wrow = tid >> 2;
    const int wc4  = (tid & 3) << 2;

#define GATHER_X(tt, dstp) do {                                                \
    const float* xsrc = X + ((size_t)(tt) * BATCH + b0) * DIN;                 \
    const int xtid_ = tid - 256;                                               \
    _Pragma("unroll")                                                          \
    for (int i_ = 0; i_ < 8; i_++) {                                           \
        int idx_ = xtid_ + i_ * 128;                                           \
        int r_   = idx_ >> 6;                                                  \
        int c_   = idx_ & 63;                                                  \
        const float* p_ = xsrc + (size_t)r_ * DIN + c_ * 8;                    \
        float4 u_ = __ldcg((const float4*)p_);                                 \
        float4 v_ = __ldcg((const float4*)(p_ + 4));                           \
        *(uint4*)((dstp) + r_ * 1024 + ((c_ ^ (r_ & 7)) << 4)) =               \
            make_uint4(pkh2(u_.x, u_.y), pkh2(u_.z, u_.w),                     \
                       pkh2(v_.x, v_.y), pkh2(v_.z, v_.w));                    \
    }                                                                          \
} while (0)

#define X_KLOOP(xbase_, gxd_) do {                                             \
    float qx0_[4] = {0.f, 0.f, 0.f, 0.f}, qx1_[4] = {0.f, 0.f, 0.f, 0.f};      \
    _Pragma("unroll")                                                          \
    for (int ks_ = 0; ks_ < 32; ks_++) {                                       \
        uint32_t kk_ = ((uint32_t)(2 * ks_) + csel) ^ lrow7;                   \
        uint32_t a0_, a1_, a2_, a3_;                                           \
        ldsm4(a0_, a1_, a2_, a3_, (xbase_) + (kk_ << 4));                      \
        uint4 wv_ = wxf4[(wx * 32 + ks_) * 32 + lane];                         \
        hmma(qx0_, a0_, a1_, a2_, a3_, wv_.x, wv_.y);                          \
        hmma(qx1_, a0_, a1_, a2_, a3_, wv_.z, wv_.w);                          \
    }                                                                          \
    (gxd_)[(2 * wx + 0) * 32 + lane] =                                         \
        make_float4(qx0_[0], qx0_[1], qx0_[2], qx0_[3]);                       \
    (gxd_)[(2 * wx + 1) * 32 + lane] =                                         \
        make_float4(qx1_[0], qx1_[1], qx1_[2], qx1_[3]);                       \
} while (0)

    // ---- prologue: x crew gathers x(0), computes Gx(0), gathers x(1) ----------
    if (!is_h) GATHER_X(0, xA0p);
    __syncthreads();
    if (!is_h) {
        X_KLOOP(x0base, gxs0);
        GATHER_X(1, xA1p);
    }
    __syncthreads();

    for (int t = 0; t < T_STEPS; t++) {
        if (is_h) {
            // ---- phase 1: spin + gather h(t-1) (h crew only) --------------------
            if (t > 0) {
                unsigned int target = (unsigned int)t * 32u;
                unsigned int v;
                do {
                    asm volatile("ld.acquire.gpu.u32 %0, [%1];" : "=r"(v) : "l"(barp));
                } while (v < target);
                const __half* hsrc = g_h16 + (size_t)((t - 1) & 1) * BATCH * HID
                                   + (size_t)b0 * HID;
#pragma unroll
                for (int i = 0; i < 4; i++) {
                    int idx = tid + i * 256;
                    int r   = idx >> 6;
                    int c   = idx & 63;
                    uint4 vv = __ldcg((const uint4*)(hsrc + (size_t)r * HID + c * 8));
                    *(uint4*)(hAp + r * 1024 + ((c ^ (r & 7)) << 4)) = vv;
                }
            }
            HBAR();   // hA ready

            // ---- phase 2: h K-half loop -----------------------------------------
            float qh0[4] = {0.f, 0.f, 0.f, 0.f}, qh1[4] = {0.f, 0.f, 0.f, 0.f};
#pragma unroll
            for (int ks = 0; ks < 16; ks++) {
                uint32_t kk = (2 * (kofs + ks) + csel) ^ lrow7;
                uint32_t a0, a1, a2, a3;
                ldsm4(a0, a1, a2, a3, lbase + (kk << 4));
                hmma(qh0, a0, a1, a2, a3, Bf[ks][0][0], Bf[ks][0][1]);
                hmma(qh1, a0, a1, a2, a3, Bf[ks][1][0], Bf[ks][1][1]);
            }
            {
                float* gh = kv ? qh0 : qh1;
                exh[w * 32 + lane] = make_float4(gh[0], gh[1], gh[2], gh[3]);
            }
            HBAR();   // exh ready

            // ---- phase 3: epilogue ----------------------------------------------
            {
                float4 ph = exh[(w ^ 1) * 32 + lane];
                float4 gx = ((t & 1) ? gxs1 : gxs0)[w * 32 + lane];
                float* kh = kv ? qh1 : qh0;
                float c0  = kh[0] + ph.x + gx.x;
                float c1  = kh[1] + ph.y + gx.y;
                float c2v = kh[2] + ph.z + gx.z;
                float c3  = kh[3] + ph.w + gx.w;

                float s0 = __shfl_xor_sync(0xffffffffu, c0, 1);
                float s1 = __shfl_xor_sync(0xffffffffu, c1, 1);
                float s2 = __shfl_xor_sync(0xffffffffu, c2v, 1);
                float s3 = __shfl_xor_sync(0xffffffffu, c3, 1);
                float pf, pi, pg, po;
                if (tg & 1) { pf = s2; pi = s3; pg = c2v; po = c3; }
                else        { pf = c0; pi = c1; pg = s0;  po = s1; }
                pf += bb.x;
                pi += bb.y;
                pg += bb.z;
                po += bb.w;

                float f  = sigf(pf);
                float ii = sigf(pi);
                float gv = tanhfast(pg);
                float oo = sigf(po);
                c_st = f * c_st + ii * gv;
                float hv = oo * tanhfast(c_st);
                hsm[myrow * 20 + lc] = hv;
            }
            HBAR();   // hsm ready

            // ---- phase 4: writers store h16, signal, then out ------------------
            float4 v4;
            if (tid < 64) {
                v4 = *(const float4*)&hsm[wrow * 20 + wc4];
                uint2 pk;
                pk.x = pkh2(v4.x, v4.y);
                pk.y = pkh2(v4.z, v4.w);
                *(uint2*)(g_h16 + (size_t)(t & 1) * BATCH * HID
                          + (size_t)(b0 + wrow) * HID + h0 + wc4) = pk;
            }
            if (t + 1 < T_STEPS) {
                HBAR();   // h16 stores done
                if (tid == 0)
                    asm volatile("red.release.gpu.global.add.u32 [%0], %1;"
                                 :: "l"(barp), "r"(1u) : "memory");
            }
            if (tid < 64) {
                *(float4*)(out + ((size_t)t * BATCH + b0 + wrow) * HID + h0 + wc4) = v4;
                if (write_tail && t == T_STEPS - 1) {
                    *(float4*)(out + (size_t)T_STEPS * BATCH * HID
                               + (size_t)(b0 + wrow) * HID + h0 + wc4) = v4;
                }
            }
        } else {
            // ---- x crew: Gx(t+1) + gather x(t+2), fully decoupled ---------------
            if (t + 1 < T_STEPS) {
                const uint32_t xbase = ((t + 1) & 1) ? x1base : x0base;
                float4* gxd = ((t + 1) & 1) ? gxs1 : gxs0;
                X_KLOOP(xbase, gxd);
            }
            if (t + 2 < T_STEPS) {
                char* xdst = (t & 1) ? xA1p : xA0p;
                GATHER_X(t + 2, xdst);
            }
        }
        __syncthreads();   // joint: publish gxs[(t+1)&1]; h done reading gxs[t&1]
    }

    // ---- tail: c state ---------------------------------------------------------
    if (write_tail) {
        if (is_h) hsm[myrow * 20 + lc] = c_st;
        __syncthreads();
        if (tid < 64) {
            float4 v4 = *(const float4*)&hsm[wrow * 20 + wc4];
            *(float4*)(out + (size_t)(T_STEPS + 1) * BATCH * HID
                       + (size_t)(b0 + wrow) * HID + h0 + wc4) = v4;
        }
    }
}

// ---------------- launch ------------------------------------------------------
extern "C" void kernel_launch(void* const* d_in, const int* in_sizes, int n_in,
                              void* d_out, int out_size) {
    const float* x  = (const float*)d_in[0];
    const float* Wf = (const float*)d_in[1];
    const float* bf = (const float*)d_in[2];
    const float* Wi = (const float*)d_in[3];
    const float* bi = (const float*)d_in[4];
    const float* Wg = (const float*)d_in[5];
    const float* bg = (const float*)d_in[6];
    const float* Wo = (const float*)d_in[7];
    const float* bo = (const float*)d_in[8];
    float* out = (float*)d_out;

    const long long tbh = (long long)T_STEPS * BATCH * HID;
    int write_tail = ((long long)out_size >= tbh + 2LL * BATCH * HID) ? 1 : 0;

    void* barp = nullptr;
    cudaGetSymbolAddress(&barp, g_bar4);
    cudaMemsetAsync(barp, 0, sizeof(unsigned int) * 4 * 32, 0);

    cudaFuncSetAttribute(lstm_kernel, cudaFuncAttributeMaxDynamicSharedMemorySize,
                         SMEM_BYTES);
    lstm_kernel<<<NBLK, NTHR, SMEM_BYTES>>>(out, write_tail, x,
                                            Wf, Wi, Wg, Wo, bf, bi, bg, bo);
}